// round 17
// baseline (speedup 1.0000x reference)
#include <cuda_runtime.h>

// Shapes fixed by reference setup_inputs(): B=4, N=M=8192, D=3.
#define B_      4
#define NPTS    8192
#define SETS    8                   // (cloud 0|1) * 4 batches; set = cloud*4 + b
#define TOTPTS  (SETS * NPTS)       // 65536

// Spatial grid: 32^3 cells over [-4, 4]^3 (h = 0.25). Coords beyond +-4 clamp
// into edge cells; the termination bound excludes grid-edge faces so clamped
// points are handled exactly.
#define GRIDN   32
#define GLO     (-4.0f)
#define H       0.25f
#define INVH    4.0f
#define C       (GRIDN * GRIDN * GRIDN)     // 32768 cells per set
#define CELLS_TOTAL (SETS * C)              // 262144
#define CPT     (C / 1024)                  // 32 cells per scan thread

// Static scratch (no cudaMalloc). g_counts is zero at module load and the
// scatter kernel's atomic DECREMENT returns every counter to exactly 0, so
// the zero-counts invariant holds across graph replays. g_done is likewise
// reset to 0 by the last reduce block each run.
__device__ int    g_counts[CELLS_TOTAL];
__device__ int    g_start[CELLS_TOTAL + 1];
__device__ float4 g_sp[TOTPTS];                 // cell-sorted (x,y,z, idx-bits)
__device__ float  g_od[TOTPTS];                 // chamfer term (orig-idx slot)
__device__ float  g_on[TOTPTS];                 // normal term  (orig-idx slot)
__device__ float  g_bs_d[256];
__device__ float  g_bs_n[256];
__device__ unsigned g_done;

__device__ __forceinline__ int cellcoord(float v) {
    int c = (int)floorf((v - GLO) * INVH);
    return min(max(c, 0), GRIDN - 1);
}

// ---------------------------------------------------------------------------
// 1) histogram (counts start at 0 by the scatter-decrement invariant)
// ---------------------------------------------------------------------------
__global__ void hist_kernel(const float* __restrict__ x1,
                            const float* __restrict__ x2)
{
    const int gid = blockIdx.x * 256 + threadIdx.x;     // 0..TOTPTS-1
    const int s = gid >> 13;
    const int t = gid & (NPTS - 1);
    const float* p = (s >= 4 ? x2 : x1) + ((size_t)(s & 3) * NPTS + t) * 3;
    const int cx = cellcoord(p[0]), cy = cellcoord(p[1]), cz = cellcoord(p[2]);
    atomicAdd(&g_counts[s * C + (cz * GRIDN + cy) * GRIDN + cx], 1);
}

// ---------------------------------------------------------------------------
// 2) single-kernel exclusive scan: 8 independent CTAs, one per set.
// ---------------------------------------------------------------------------
__global__ __launch_bounds__(1024)
void scan_kernel()
{
    __shared__ int sh[1024];
    const int s   = blockIdx.x;
    const int tid = threadIdx.x;
    const int base = s * C + tid * CPT;

    int vals[CPT];
    const int4* cp = (const int4*)(g_counts + base);
#pragma unroll
    for (int v = 0; v < CPT / 4; v++) {
        const int4 x = cp[v];
        vals[4 * v + 0] = x.x; vals[4 * v + 1] = x.y;
        vals[4 * v + 2] = x.z; vals[4 * v + 3] = x.w;
    }
    int acc = 0;
#pragma unroll
    for (int i = 0; i < CPT; i++) { const int v = vals[i]; vals[i] = acc; acc += v; }

    sh[tid] = acc;
    __syncthreads();
#pragma unroll
    for (int off = 1; off < 1024; off <<= 1) {
        int t2 = (tid >= off) ? sh[tid - off] : 0;
        __syncthreads();
        sh[tid] += t2;
        __syncthreads();
    }
    const int tbase = s * NPTS + (sh[tid] - acc);       // set base + exclusive

    int4* op = (int4*)(g_start + base);
#pragma unroll
    for (int v = 0; v < CPT / 4; v++)
        op[v] = make_int4(tbase + vals[4 * v + 0], tbase + vals[4 * v + 1],
                          tbase + vals[4 * v + 2], tbase + vals[4 * v + 3]);
    if (s == SETS - 1 && tid == 1023) g_start[CELLS_TOTAL] = TOTPTS;
}

// ---------------------------------------------------------------------------
// 3) scatter with atomic DECREMENT -> counters end at exactly 0 (invariant)
// ---------------------------------------------------------------------------
__global__ void scatter_kernel(const float* __restrict__ x1,
                               const float* __restrict__ x2)
{
    const int gid = blockIdx.x * 256 + threadIdx.x;
    const int s = gid >> 13;
    const int t = gid & (NPTS - 1);
    const float* p = (s >= 4 ? x2 : x1) + ((size_t)(s & 3) * NPTS + t) * 3;
    const float vx = p[0], vy = p[1], vz = p[2];
    const int cx = cellcoord(vx), cy = cellcoord(vy), cz = cellcoord(vz);
    const int cid = s * C + (cz * GRIDN + cy) * GRIDN + cx;
    const int pos = g_start[cid] + atomicAdd(&g_counts[cid], -1) - 1;
    g_sp[pos] = make_float4(vx, vy, vz, __int_as_float(t));
}

// ---------------------------------------------------------------------------
// 4) NN search: FOUR queries per warp, EIGHT lanes per query. Queries are
// cell-sorted, so the 4 groups' control flow is nearly identical and the
// SIMT union costs ~1 query's instructions (~4x fewer warps than
// warp-per-query, evals/lane 2.5 -> 10). Per group: its 9 (or 25) row
// ranges are fetched by its 8 lanes in parallel into per-group shared
// slots (group-local __syncwarp(gmask)); each row's CONTIGUOUS candidates
// are strided by 8 (coalesced); merge of (d, oid) lexicographic via
// shfl.xor over the 8 lanes = serial-scan result, independent of bin order.
// Stage 1: 3^3 box (bound >= 1 cell). Stage 2: 5^3 box (bound >= 2 cells;
// re-scan harmless, min idempotent). Stage 3 (rare): exact brute force.
// ---------------------------------------------------------------------------
__global__ __launch_bounds__(128)
void nn_search_kernel(const float* __restrict__ n1,
                      const float* __restrict__ n2)
{
    __shared__ int2 rows[4][4][25];                     // [warp][group][row]

    const int tid   = threadIdx.x;
    const int wid   = tid >> 5;
    const int lane  = tid & 31;
    const int grp   = (lane >> 3);                      // 0..3
    const int glane = lane & 7;                         // 0..7
    const unsigned gmask = 0xFFu << (lane & 24);        // this 8-lane group

    const int qid = (blockIdx.x * 128 + tid) >> 3;      // 0..TOTPTS-1
    const int s = qid >> 13;
    const int t = qid & (NPTS - 1);
    const int g = s ^ 4;
    const int b = s & 3;

    const float4 q = g_sp[s * NPTS + t];
    const int qorig = __float_as_int(q.w);
    const int cx = cellcoord(q.x), cy = cellcoord(q.y), cz = cellcoord(q.z);

    float bestd = 3.4e38f;
    int   bidx  = 0x7FFFFFFF;
    const int gC = g * C;

    auto eval = [&](int j) {
        const float4 p = g_sp[j];
        const float dx = q.x - p.x, dy = q.y - p.y, dz = q.z - p.z;
        const float d = dx * dx + dy * dy + dz * dz;
        const int oid = __float_as_int(p.w);
        if (d < bestd || (d == bestd && oid < bidx)) { bestd = d; bidx = oid; }
    };
    auto merge8 = [&]() {
#pragma unroll
        for (int m = 1; m < 8; m <<= 1) {
            const float od = __shfl_xor_sync(gmask, bestd, m);
            const int   oi = __shfl_xor_sync(gmask, bidx,  m);
            if (od < bestd || (od == bestd && oi < bidx)) { bestd = od; bidx = oi; }
        }
    };
    // scan a box of half-width r (nrows = side*side rows): ranges fetched by
    // the group's 8 lanes into the group's shared slots, then each row's
    // contiguous candidates strided across the 8 lanes.
    auto scan_box = [&](int r, int nrows, int side) {
        const int x0 = max(cx - r, 0), x1 = min(cx + r, GRIDN - 1);
        const int nx = x1 - x0 + 1;
        for (int i = glane; i < nrows; i += 8) {
            const int z = min(max(cz + (i / side) - r, 0), GRIDN - 1);
            const int y = min(max(cy + (i % side) - r, 0), GRIDN - 1);
            const int cid = gC + (z * GRIDN + y) * GRIDN + x0;
            rows[wid][grp][i] = make_int2(g_start[cid], g_start[cid + nx]);
        }
        __syncwarp(gmask);
        for (int i = 0; i < nrows; i++) {
            const int2 rg = rows[wid][grp][i];          // group-broadcast LDS.64
            for (int j = rg.x + glane; j < rg.y; j += 8) eval(j);
        }
        __syncwarp(gmask);
    };
    // min distance from q to the region outside the searched box of
    // half-width r (grid-edge faces excluded; clamped outliers are in edge
    // cells which are scanned exactly).
    auto boxbound = [&](int r) {
        float bnd = 1e30f;
        int e;
        e = cx - r; if (e > 0)          bnd = fminf(bnd, q.x - (GLO + e * H));
        e = cx + r; if (e < GRIDN - 1)  bnd = fminf(bnd, (GLO + (e + 1) * H) - q.x);
        e = cy - r; if (e > 0)          bnd = fminf(bnd, q.y - (GLO + e * H));
        e = cy + r; if (e < GRIDN - 1)  bnd = fminf(bnd, (GLO + (e + 1) * H) - q.y);
        e = cz - r; if (e > 0)          bnd = fminf(bnd, q.z - (GLO + e * H));
        e = cz + r; if (e < GRIDN - 1)  bnd = fminf(bnd, (GLO + (e + 1) * H) - q.z);
        return fmaxf(bnd, 0.0f);
    };

    // stage 1: 3^3 box (9 rows)
    scan_box(1, 9, 3);
    merge8();
    float bnd = boxbound(1);

    if (!(bestd < bnd * bnd)) {                         // group-uniform
        // stage 2: 5^3 box (25 rows)
        scan_box(2, 25, 5);
        merge8();
        bnd = boxbound(2);
        if (!(bestd < bnd * bnd)) {
            // stage 3: exact brute force over the whole target set
#pragma unroll 4
            for (int j = g * NPTS + glane; j < (g + 1) * NPTS; j += 8) eval(j);
            merge8();
        }
    }

    // group lane 0: normal term + write (orig-idx slot => deterministic)
    if (glane == 0) {
        const float* qn = (s >= 4 ? n2 : n1) + ((size_t)b * NPTS + qorig) * 3;
        const float* tn = (s >= 4 ? n1 : n2) + ((size_t)b * NPTS + bidx) * 3;
        const float dotp = qn[0] * tn[0] + qn[1] * tn[1] + qn[2] * tn[2];
        float na = sqrtf(qn[0] * qn[0] + qn[1] * qn[1] + qn[2] * qn[2]);
        float nb = sqrtf(tn[0] * tn[0] + tn[1] * tn[1] + tn[2] * tn[2]);
        na = fmaxf(na, 1e-6f);
        nb = fmaxf(nb, 1e-6f);
        const int slot = s * NPTS + qorig;
        g_od[slot] = bestd;
        g_on[slot] = 1.0f - fabsf(dotp / (na * nb));
    }
}

// ---------------------------------------------------------------------------
// 5) fused reduction: 256 blocks produce block sums; the LAST block (atomic
// counter + threadfence) tree-sums the 256 block sums in fixed index order
// (fully deterministic) and writes the two outputs, then resets the counter
// for the next graph replay.
// ---------------------------------------------------------------------------
__global__ __launch_bounds__(256)
void reduce_final_kernel(float* __restrict__ out)
{
    __shared__ float sd[256];
    __shared__ float sn[256];
    __shared__ bool  s_last;
    const int tid = threadIdx.x;
    const int i = blockIdx.x * 256 + tid;
    sd[tid] = g_od[i];
    sn[tid] = g_on[i];
    __syncthreads();
#pragma unroll
    for (int o = 128; o > 0; o >>= 1) {
        if (tid < o) { sd[tid] += sd[tid + o]; sn[tid] += sn[tid + o]; }
        __syncthreads();
    }
    if (tid == 0) {
        g_bs_d[blockIdx.x] = sd[0];
        g_bs_n[blockIdx.x] = sn[0];
        __threadfence();
        s_last = (atomicAdd(&g_done, 1u) == 255u);
    }
    __syncthreads();
    if (!s_last) return;

    // last block: deterministic fixed-order tree over the completed array
    sd[tid] = g_bs_d[tid];
    sn[tid] = g_bs_n[tid];
    __syncthreads();
#pragma unroll
    for (int o = 128; o > 0; o >>= 1) {
        if (tid < o) { sd[tid] += sd[tid + o]; sn[tid] += sn[tid + o]; }
        __syncthreads();
    }
    if (tid == 0) {
        const float inv = 1.0f / (float)(B_ * NPTS);
        out[0] = sd[0] * inv;
        out[1] = sn[0] * inv;
        g_done = 0;                                     // reset for next replay
    }
}

extern "C" void kernel_launch(void* const* d_in, const int* in_sizes, int n_in,
                              void* d_out, int out_size)
{
    const float* xyz1  = (const float*)d_in[0];
    const float* xyz2  = (const float*)d_in[1];
    const float* nxyz1 = (const float*)d_in[2];
    const float* nxyz2 = (const float*)d_in[3];
    float* out = (float*)d_out;

    hist_kernel<<<TOTPTS / 256, 256>>>(xyz1, xyz2);
    scan_kernel<<<SETS, 1024>>>();
    scatter_kernel<<<TOTPTS / 256, 256>>>(xyz1, xyz2);
    nn_search_kernel<<<TOTPTS * 8 / 128, 128>>>(nxyz1, nxyz2);    // 4096 CTAs
    reduce_final_kernel<<<TOTPTS / 256, 256>>>(out);
}